// round 6
// baseline (speedup 1.0000x reference)
#include <cuda_runtime.h>
#include <cstdint>

#define NNODES 100000
#define NEDGES 640000
#define FIN 128
#define FOUT 64
#define BN_EPS 1e-5f
#define SCAN_BS 256
#define MAX_BLOCKS 512   // ceil(NNODES/SCAN_BS) = 391 < 512

// ---------------- scratch (static device globals; no runtime allocation) ----
__device__ float g_h[(size_t)NNODES * FIN];     // x @ W_gcn
__device__ float g_agg[(size_t)NNODES * FIN];   // aggregated messages
__device__ float g_t[(size_t)NNODES * FOUT];    // hidden after GEMM2
__device__ int   g_degi[NNODES];
__device__ float g_dinv[NNODES];
__device__ int   g_off[NNODES + 1];
__device__ int   g_cursor[NNODES];
__device__ int   g_bsum[MAX_BLOCKS];
__device__ int   g_boff[MAX_BLOCKS];
__device__ int   g_elist[NEDGES];
__device__ float g_sum1[FIN], g_sq1[FIN], g_a1[FIN], g_c1[FIN];
__device__ float g_sum2[FOUT], g_sq2[FOUT], g_a2[FOUT], g_c2[FOUT];

// ---------------- zero ------------------------------------------------------
__global__ void zero_kernel(int M) {
    int i = blockIdx.x * blockDim.x + threadIdx.x;
    for (int j = i; j < M; j += gridDim.x * blockDim.x) g_degi[j] = 0;
    if (i < FIN)  { g_sum1[i] = 0.f; g_sq1[i] = 0.f; }
    if (i < FOUT) { g_sum2[i] = 0.f; g_sq2[i] = 0.f; }
}

// ---------------- in-degree count -------------------------------------------
__global__ void deg_kernel(const int* __restrict__ dst, int E, int M) {
    int e = blockIdx.x * blockDim.x + threadIdx.x;
    if (e < E) {
        int d = dst[e];
        if ((unsigned)d < (unsigned)M) atomicAdd(&g_degi[d], 1);
    }
}

// ---------------- prefix scan (3 kernels) -----------------------------------
__global__ void scan1_kernel(int M) {
    __shared__ int sh[SCAN_BS];
    int i = blockIdx.x * SCAN_BS + threadIdx.x;
    int v = (i < M) ? g_degi[i] : 0;
    sh[threadIdx.x] = v;
    __syncthreads();
    #pragma unroll
    for (int ofs = 1; ofs < SCAN_BS; ofs <<= 1) {
        int t = 0;
        if (threadIdx.x >= ofs) t = sh[threadIdx.x - ofs];
        __syncthreads();
        sh[threadIdx.x] += t;
        __syncthreads();
    }
    if (i < M) g_off[i] = sh[threadIdx.x] - v;          // exclusive within block
    if (threadIdx.x == SCAN_BS - 1) g_bsum[blockIdx.x] = sh[SCAN_BS - 1];
}

__global__ void scan2_kernel(int NB) {
    __shared__ int sh[MAX_BLOCKS];
    int t = threadIdx.x;
    int v = (t < NB) ? g_bsum[t] : 0;
    sh[t] = v;
    __syncthreads();
    #pragma unroll
    for (int ofs = 1; ofs < MAX_BLOCKS; ofs <<= 1) {
        int u = 0;
        if (t >= ofs) u = sh[t - ofs];
        __syncthreads();
        sh[t] += u;
        __syncthreads();
    }
    if (t < NB) g_boff[t] = sh[t] - v;                   // exclusive block offset
}

__global__ void scan3_kernel(int M, int E) {
    int i = blockIdx.x * blockDim.x + threadIdx.x;
    if (i < M) {
        int o = g_off[i] + g_boff[i / SCAN_BS];
        g_off[i] = o;
        g_cursor[i] = o;
        g_dinv[i] = rsqrtf((float)g_degi[i] + 1.0f);  // +1 = self loop (fused)
    }
    if (i == 0) g_off[M] = E;
}

// ---------------- edge-list fill --------------------------------------------
__global__ void fill_kernel(const int* __restrict__ src, const int* __restrict__ dst,
                            int E, int M) {
    int e = blockIdx.x * blockDim.x + threadIdx.x;
    if (e < E) {
        int s = src[e];
        int d = dst[e];
        if ((unsigned)s < (unsigned)M && (unsigned)d < (unsigned)M) {
            int p = atomicAdd(&g_cursor[d], 1);
            g_elist[p] = s;
        }
    }
}

// ---------------- gather + fused BN1 partial stats --------------------------
// agg[d] = dinv[d]*sum(dinv[s]*h[s]) + dinv[d]^2*h[d]
// one warp per node (8 nodes/block); lane l covers feature cols 4l..4l+3.
// Block-reduces column sum/sumsq of its 8 agg rows, one atomicAdd per column.
__global__ void gather_kernel(int M) {
    __shared__ float s_s[8][FIN];
    __shared__ float s_q[8][FIN];
    int w = threadIdx.x >> 5;
    int lane = threadIdx.x & 31;
    int node = blockIdx.x * 8 + w;

    float4 o = make_float4(0.f, 0.f, 0.f, 0.f);
    if (node < M) {
        int d = node;
        int e0 = g_off[d];
        int e1 = g_cursor[d];
        float4 acc0 = make_float4(0.f, 0.f, 0.f, 0.f);
        float4 acc1 = make_float4(0.f, 0.f, 0.f, 0.f);
        int e = e0;
        for (; e + 1 < e1; e += 2) {
            int s0 = g_elist[e];
            int s1 = g_elist[e + 1];
            float w0 = g_dinv[s0];
            float w1 = g_dinv[s1];
            float4 v0 = *(const float4*)&g_h[(size_t)s0 * FIN + lane * 4];
            float4 v1 = *(const float4*)&g_h[(size_t)s1 * FIN + lane * 4];
            acc0.x = fmaf(v0.x, w0, acc0.x); acc1.x = fmaf(v1.x, w1, acc1.x);
            acc0.y = fmaf(v0.y, w0, acc0.y); acc1.y = fmaf(v1.y, w1, acc1.y);
            acc0.z = fmaf(v0.z, w0, acc0.z); acc1.z = fmaf(v1.z, w1, acc1.z);
            acc0.w = fmaf(v0.w, w0, acc0.w); acc1.w = fmaf(v1.w, w1, acc1.w);
        }
        if (e < e1) {
            int s0 = g_elist[e];
            float w0 = g_dinv[s0];
            float4 v0 = *(const float4*)&g_h[(size_t)s0 * FIN + lane * 4];
            acc0.x = fmaf(v0.x, w0, acc0.x);
            acc0.y = fmaf(v0.y, w0, acc0.y);
            acc0.z = fmaf(v0.z, w0, acc0.z);
            acc0.w = fmaf(v0.w, w0, acc0.w);
        }
        float wd = g_dinv[d];
        float4 vs = *(const float4*)&g_h[(size_t)d * FIN + lane * 4];
        o.x = wd * (acc0.x + acc1.x) + wd * wd * vs.x;
        o.y = wd * (acc0.y + acc1.y) + wd * wd * vs.y;
        o.z = wd * (acc0.z + acc1.z) + wd * wd * vs.z;
        o.w = wd * (acc0.w + acc1.w) + wd * wd * vs.w;
        *(float4*)&g_agg[(size_t)d * FIN + lane * 4] = o;
    }

    // stats partials (zeros for inactive warps)
    int c0 = lane * 4;
    s_s[w][c0 + 0] = o.x; s_s[w][c0 + 1] = o.y; s_s[w][c0 + 2] = o.z; s_s[w][c0 + 3] = o.w;
    s_q[w][c0 + 0] = o.x * o.x; s_q[w][c0 + 1] = o.y * o.y;
    s_q[w][c0 + 2] = o.z * o.z; s_q[w][c0 + 3] = o.w * o.w;
    __syncthreads();

    int col = threadIdx.x & 127;
    if (threadIdx.x < 128) {
        float v = 0.f;
        #pragma unroll
        for (int k = 0; k < 8; k++) v += s_s[k][col];
        atomicAdd(&g_sum1[col], v);
    } else {
        float v = 0.f;
        #pragma unroll
        for (int k = 0; k < 8; k++) v += s_q[k][col];
        atomicAdd(&g_sq1[col], v);
    }
}

// ---------------- per-column sum / sumsq (for BN2 only) ---------------------
template <int F>
__global__ void stats_kernel(const float* __restrict__ X, int M,
                             float* __restrict__ sum, float* __restrict__ sq) {
    constexpr int RP = 256 / F;
    int col  = threadIdx.x % F;
    int rsub = threadIdx.x / F;
    float s = 0.f, q = 0.f;
    for (int r = blockIdx.x * RP + rsub; r < M; r += gridDim.x * RP) {
        float v = X[(size_t)r * F + col];
        s += v; q += v * v;
    }
    __shared__ float sh[256];
    sh[threadIdx.x] = s; __syncthreads();
    if (rsub == 0) {
        #pragma unroll
        for (int k = 1; k < RP; k++) s += sh[k * F + col];
    }
    __syncthreads();
    sh[threadIdx.x] = q; __syncthreads();
    if (rsub == 0) {
        #pragma unroll
        for (int k = 1; k < RP; k++) q += sh[k * F + col];
        atomicAdd(&sum[col], s);
        atomicAdd(&sq[col],  q);
    }
}

template <int F>
__global__ void finalize_kernel(const float* __restrict__ sum, const float* __restrict__ sq,
                                const float* __restrict__ gamma, const float* __restrict__ beta,
                                int M, float* __restrict__ a, float* __restrict__ c) {
    int i = threadIdx.x;
    if (i < F) {
        float mean = sum[i] / (float)M;
        float var  = sq[i] / (float)M - mean * mean;
        float s = gamma[i] * rsqrtf(var + BN_EPS);
        a[i] = s;
        c[i] = beta[i] - mean * s;
    }
}

// ---------------- SGEMM (single-buffer, BK=16) ------------------------------
// C[M,N] = act(A)[M,K] @ B[K,N]; act = relu(a*x+c) per K-column when BNIN.
template <int N, int K, bool BNIN, bool BIAS>
__global__ __launch_bounds__(256) void sgemm_kernel(
    const float* __restrict__ A, const float* __restrict__ B, float* __restrict__ C,
    int M, const float* __restrict__ sc, const float* __restrict__ shf,
    const float* __restrict__ bias) {
    constexpr int BM = 128, BK = 16, TM = 8, TN = N / 16;
    constexpr int APT = (BM * BK / 4) / 256;       // 2
    constexpr int BPT = (BK * N / 4) / 256;        // 2 (N=128) or 1 (N=64)
    __shared__ float As[BK][BM + 4];
    __shared__ float Bs[BK][N];
    __shared__ float s_sc[K], s_sh[K];

    int tid = threadIdx.x;
    if (BNIN) {
        for (int i = tid; i < K; i += 256) { s_sc[i] = sc[i]; s_sh[i] = shf[i]; }
        __syncthreads();
    }

    int tx = tid & 15, ty = tid >> 4;
    int row0 = blockIdx.x * BM;

    float acc[TM][TN];
    #pragma unroll
    for (int i = 0; i < TM; i++)
        #pragma unroll
        for (int j = 0; j < TN; j++) acc[i][j] = 0.f;

    for (int k0 = 0; k0 < K; k0 += BK) {
        #pragma unroll
        for (int p = 0; p < APT; p++) {
            int f = tid + p * 256;
            int r = f >> 2;
            int kk4 = (f & 3) * 4;
            float4 av = make_float4(0.f, 0.f, 0.f, 0.f);
            if (row0 + r < M) av = *(const float4*)&A[(size_t)(row0 + r) * K + k0 + kk4];
            if (BNIN) {
                int kb = k0 + kk4;
                av.x = fmaxf(fmaf(av.x, s_sc[kb + 0], s_sh[kb + 0]), 0.f);
                av.y = fmaxf(fmaf(av.y, s_sc[kb + 1], s_sh[kb + 1]), 0.f);
                av.z = fmaxf(fmaf(av.z, s_sc[kb + 2], s_sh[kb + 2]), 0.f);
                av.w = fmaxf(fmaf(av.w, s_sc[kb + 3], s_sh[kb + 3]), 0.f);
            }
            As[kk4 + 0][r] = av.x; As[kk4 + 1][r] = av.y;
            As[kk4 + 2][r] = av.z; As[kk4 + 3][r] = av.w;
        }
        #pragma unroll
        for (int p = 0; p < BPT; p++) {
            int g = tid + p * 256;
            int kr = g / (N / 4);
            int c4 = (g % (N / 4)) * 4;
            *(float4*)&Bs[kr][c4] = *(const float4*)&B[(size_t)(k0 + kr) * N + c4];
        }
        __syncthreads();

        #pragma unroll
        for (int kk = 0; kk < BK; kk++) {
            float a[TM], b[TN];
            *(float4*)&a[0] = *(const float4*)&As[kk][ty * TM];
            *(float4*)&a[4] = *(const float4*)&As[kk][ty * TM + 4];
            #pragma unroll
            for (int j = 0; j < TN; j += 4)
                *(float4*)&b[j] = *(const float4*)&Bs[kk][tx * TN + j];
            #pragma unroll
            for (int i = 0; i < TM; i++)
                #pragma unroll
                for (int j = 0; j < TN; j++)
                    acc[i][j] = fmaf(a[i], b[j], acc[i][j]);
        }
        __syncthreads();
    }

    float bj[TN];
    if (BIAS) {
        #pragma unroll
        for (int j = 0; j < TN; j++) bj[j] = bias[tx * TN + j];
    }
    #pragma unroll
    for (int i = 0; i < TM; i++) {
        int grow = row0 + ty * TM + i;
        if (grow < M) {
            #pragma unroll
            for (int j = 0; j < TN; j += 4) {
                float4 v;
                v.x = acc[i][j]; v.y = acc[i][j + 1];
                v.z = acc[i][j + 2]; v.w = acc[i][j + 3];
                if (BIAS) { v.x += bj[j]; v.y += bj[j + 1]; v.z += bj[j + 2]; v.w += bj[j + 3]; }
                *(float4*)&C[(size_t)grow * N + tx * TN + j] = v;
            }
        }
    }
}

// ---------------- launch ----------------------------------------------------
extern "C" void kernel_launch(void* const* d_in, const int* in_sizes, int n_in,
                              void* d_out, int out_size) {
    const float* x     = (const float*)d_in[0];
    const int*   ei    = (const int*)d_in[1];
    const float* W_gcn = (const float*)d_in[2];
    // d_in[3] = b_gcn : exactly absorbed by BN1 (mean-subtraction) -> unused
    const float* bn_g  = (const float*)d_in[4];
    const float* bn_b  = (const float*)d_in[5];
    const float* W1    = (const float*)d_in[6];
    // d_in[7] = b1    : exactly absorbed by BN2 -> unused
    const float* mg    = (const float*)d_in[8];
    const float* mb    = (const float*)d_in[9];
    const float* W2    = (const float*)d_in[10];
    const float* b2    = (const float*)d_in[11];
    float* out = (float*)d_out;

    int M = in_sizes[0] / FIN;
    int E = in_sizes[1] / 2;
    const int* src = ei;
    const int* dst = ei + E;
    int NB = (M + SCAN_BS - 1) / SCAN_BS;

    void *p_h, *p_agg, *p_t, *p_sum1, *p_sq1, *p_a1, *p_c1, *p_sum2, *p_sq2, *p_a2, *p_c2;
    cudaGetSymbolAddress(&p_h, g_h);
    cudaGetSymbolAddress(&p_agg, g_agg);
    cudaGetSymbolAddress(&p_t, g_t);
    cudaGetSymbolAddress(&p_sum1, g_sum1);
    cudaGetSymbolAddress(&p_sq1, g_sq1);
    cudaGetSymbolAddress(&p_a1, g_a1);
    cudaGetSymbolAddress(&p_c1, g_c1);
    cudaGetSymbolAddress(&p_sum2, g_sum2);
    cudaGetSymbolAddress(&p_sq2, g_sq2);
    cudaGetSymbolAddress(&p_a2, g_a2);
    cudaGetSymbolAddress(&p_c2, g_c2);

    // index machinery
    zero_kernel<<<256, 256>>>(M);
    deg_kernel<<<(E + 255) / 256, 256>>>(dst, E, M);
    scan1_kernel<<<NB, SCAN_BS>>>(M);
    scan2_kernel<<<1, MAX_BLOCKS>>>(NB);
    scan3_kernel<<<NB, SCAN_BS>>>(M, E);
    fill_kernel<<<(E + 255) / 256, 256>>>(src, dst, E, M);

    // GEMM1: h = x @ W_gcn
    sgemm_kernel<FIN, FIN, false, false><<<(M + 127) / 128, 256>>>(
        x, W_gcn, (float*)p_h, M, nullptr, nullptr, nullptr);

    // CSR gather + fused BN1 stats
    gather_kernel<<<(M + 7) / 8, 256>>>(M);
    finalize_kernel<FIN><<<1, 128>>>((const float*)p_sum1, (const float*)p_sq1,
                                     bn_g, bn_b, M, (float*)p_a1, (float*)p_c1);

    // GEMM2: t = relu(BN1(agg)) @ W1   (b1 absorbed by BN2)
    sgemm_kernel<FOUT, FIN, true, false><<<(M + 127) / 128, 256>>>(
        (const float*)p_agg, W1, (float*)p_t, M,
        (const float*)p_a1, (const float*)p_c1, nullptr);

    // BN2 stats
    stats_kernel<FOUT><<<1024, 256>>>((const float*)p_t, M, (float*)p_sum2, (float*)p_sq2);
    finalize_kernel<FOUT><<<1, 64>>>((const float*)p_sum2, (const float*)p_sq2,
                                     mg, mb, M, (float*)p_a2, (float*)p_c2);

    // GEMM3: out = relu(BN2(t)) @ W2 + b2
    sgemm_kernel<FOUT, FOUT, true, true><<<(M + 127) / 128, 256>>>(
        (const float*)p_t, W2, out, M,
        (const float*)p_a2, (const float*)p_c2, b2);
}

// round 8
// speedup vs baseline: 1.4732x; 1.4732x over previous
#include <cuda_runtime.h>
#include <cstdint>

#define NNODES 100000
#define NEDGES 640000
#define FIN 128
#define FOUT 64
#define BN_EPS 1e-5f
#define SCAN_BS 256
#define MAX_BLOCKS 512   // ceil(NNODES/SCAN_BS) = 391 < 512

// ---------------- scratch (static device globals; no runtime allocation) ----
__device__ float g_h[(size_t)NNODES * FIN];     // x @ W_gcn
__device__ float g_agg[(size_t)NNODES * FIN];   // aggregated messages
__device__ float g_t[(size_t)NNODES * FOUT];    // hidden after GEMM2
__device__ int   g_degi[NNODES];
__device__ float g_dinv[NNODES];
__device__ int   g_off[NNODES + 1];
__device__ int   g_cursor[NNODES];
__device__ int   g_bsum[MAX_BLOCKS];
__device__ int   g_boff[MAX_BLOCKS];
__device__ int   g_elist[NEDGES];
__device__ float g_sum1[FIN], g_sq1[FIN], g_a1[FIN], g_c1[FIN];
__device__ float g_sum2[FOUT], g_sq2[FOUT], g_a2[FOUT], g_c2[FOUT];

// ---------------- zero ------------------------------------------------------
__global__ void zero_kernel(int M) {
    int i = blockIdx.x * blockDim.x + threadIdx.x;
    for (int j = i; j < M; j += gridDim.x * blockDim.x) g_degi[j] = 0;
    if (i < FIN)  { g_sum1[i] = 0.f; g_sq1[i] = 0.f; }
    if (i < FOUT) { g_sum2[i] = 0.f; g_sq2[i] = 0.f; }
}

// ---------------- in-degree count -------------------------------------------
__global__ void deg_kernel(const int* __restrict__ dst, int E, int M) {
    int e = blockIdx.x * blockDim.x + threadIdx.x;
    if (e < E) {
        int d = dst[e];
        if ((unsigned)d < (unsigned)M) atomicAdd(&g_degi[d], 1);
    }
}

// ---------------- prefix scan (3 kernels) -----------------------------------
__global__ void scan1_kernel(int M) {
    __shared__ int sh[SCAN_BS];
    int i = blockIdx.x * SCAN_BS + threadIdx.x;
    int v = (i < M) ? g_degi[i] : 0;
    sh[threadIdx.x] = v;
    __syncthreads();
    #pragma unroll
    for (int ofs = 1; ofs < SCAN_BS; ofs <<= 1) {
        int t = 0;
        if (threadIdx.x >= ofs) t = sh[threadIdx.x - ofs];
        __syncthreads();
        sh[threadIdx.x] += t;
        __syncthreads();
    }
    if (i < M) g_off[i] = sh[threadIdx.x] - v;
    if (threadIdx.x == SCAN_BS - 1) g_bsum[blockIdx.x] = sh[SCAN_BS - 1];
}

__global__ void scan2_kernel(int NB) {
    __shared__ int sh[MAX_BLOCKS];
    int t = threadIdx.x;
    int v = (t < NB) ? g_bsum[t] : 0;
    sh[t] = v;
    __syncthreads();
    #pragma unroll
    for (int ofs = 1; ofs < MAX_BLOCKS; ofs <<= 1) {
        int u = 0;
        if (t >= ofs) u = sh[t - ofs];
        __syncthreads();
        sh[t] += u;
        __syncthreads();
    }
    if (t < NB) g_boff[t] = sh[t] - v;
}

__global__ void scan3_kernel(int M, int E) {
    int i = blockIdx.x * blockDim.x + threadIdx.x;
    if (i < M) {
        int o = g_off[i] + g_boff[i / SCAN_BS];
        g_off[i] = o;
        g_cursor[i] = o;
        g_dinv[i] = rsqrtf((float)g_degi[i] + 1.0f);  // +1 = self loop
    }
    if (i == 0) g_off[M] = E;
}

// ---------------- edge-list fill --------------------------------------------
__global__ void fill_kernel(const int* __restrict__ src, const int* __restrict__ dst,
                            int E, int M) {
    int e = blockIdx.x * blockDim.x + threadIdx.x;
    if (e < E) {
        int s = src[e];
        int d = dst[e];
        if ((unsigned)s < (unsigned)M && (unsigned)d < (unsigned)M) {
            int p = atomicAdd(&g_cursor[d], 1);
            g_elist[p] = s;
        }
    }
}

// ---------------- gather (R4 exact) -----------------------------------------
__global__ void gather_kernel(int M) {
    int warp = (blockIdx.x * blockDim.x + threadIdx.x) >> 5;
    int lane = threadIdx.x & 31;
    if (warp >= M) return;
    int d = warp;
    int e0 = g_off[d];
    int e1 = g_cursor[d];
    float4 acc = make_float4(0.f, 0.f, 0.f, 0.f);
    for (int e = e0; e < e1; e++) {
        int s = g_elist[e];
        float ws = g_dinv[s];
        float4 v = *(const float4*)&g_h[(size_t)s * FIN + lane * 4];
        acc.x = fmaf(v.x, ws, acc.x);
        acc.y = fmaf(v.y, ws, acc.y);
        acc.z = fmaf(v.z, ws, acc.z);
        acc.w = fmaf(v.w, ws, acc.w);
    }
    float wd = g_dinv[d];
    float4 vs = *(const float4*)&g_h[(size_t)d * FIN + lane * 4];
    float4 o;
    o.x = wd * acc.x + wd * wd * vs.x;
    o.y = wd * acc.y + wd * wd * vs.y;
    o.z = wd * acc.z + wd * wd * vs.z;
    o.w = wd * acc.w + wd * wd * vs.w;
    *(float4*)&g_agg[(size_t)d * FIN + lane * 4] = o;
}

// ---------------- per-column sum / sumsq ------------------------------------
template <int F>
__global__ void stats_kernel(const float* __restrict__ X, int M,
                             float* __restrict__ sum, float* __restrict__ sq) {
    constexpr int RP = 256 / F;
    int col  = threadIdx.x % F;
    int rsub = threadIdx.x / F;
    float s = 0.f, q = 0.f;
    for (int r = blockIdx.x * RP + rsub; r < M; r += gridDim.x * RP) {
        float v = X[(size_t)r * F + col];
        s += v; q += v * v;
    }
    __shared__ float sh[256];
    sh[threadIdx.x] = s; __syncthreads();
    if (rsub == 0) {
        #pragma unroll
        for (int k = 1; k < RP; k++) s += sh[k * F + col];
    }
    __syncthreads();
    sh[threadIdx.x] = q; __syncthreads();
    if (rsub == 0) {
        #pragma unroll
        for (int k = 1; k < RP; k++) q += sh[k * F + col];
        atomicAdd(&sum[col], s);
        atomicAdd(&sq[col],  q);
    }
}

template <int F>
__global__ void finalize_kernel(const float* __restrict__ sum, const float* __restrict__ sq,
                                const float* __restrict__ gamma, const float* __restrict__ beta,
                                int M, float* __restrict__ a, float* __restrict__ c) {
    int i = threadIdx.x;
    if (i < F) {
        float mean = sum[i] / (float)M;
        float var  = sq[i] / (float)M - mean * mean;
        float s = gamma[i] * rsqrtf(var + BN_EPS);
        a[i] = s;
        c[i] = beta[i] - mean * s;
    }
}

// ---------------- tf32 tensor-core GEMM1: h = x @ W  (M x 128 x 128) --------
// cvt.rna.tf32.f32 has a b32 destination -> return the raw bits in a u32.
__device__ __forceinline__ uint32_t f_tf32(float x) {
    uint32_t y;
    asm("cvt.rna.tf32.f32 %0, %1;" : "=r"(y) : "f"(x));
    return y;
}

__global__ __launch_bounds__(256) void tgemm1_kernel(
    const float* __restrict__ A, const float* __restrict__ B, float* __restrict__ C, int M) {
    constexpr int BM = 128, BN = 128, BK = 32;
    __shared__ uint32_t As[BM][BK + 4];    // bank = (4r + k) % 32 for frag reads: conflict-free
    __shared__ uint32_t Bs[BK][BN + 8];    // bank = (8k + n) % 32 for frag reads: conflict-free

    int tid = threadIdx.x;
    int lane = tid & 31, wid = tid >> 5;
    int wr = wid & 3, wc = wid >> 2;        // warp tile: 32 rows x 64 cols
    int m0 = wr * 32, n0 = wc * 64;
    int row0 = blockIdx.x * BM;
    int grp = lane >> 2, tig = lane & 3;

    float acc[2][8][4];
    #pragma unroll
    for (int i = 0; i < 2; i++)
        #pragma unroll
        for (int j = 0; j < 8; j++)
            #pragma unroll
            for (int r = 0; r < 4; r++) acc[i][j][r] = 0.f;

    for (int k0 = 0; k0 < 128; k0 += BK) {
        // A tile: 128 x 32 -> 1024 float4, 4 per thread
        #pragma unroll
        for (int p = 0; p < 4; p++) {
            int f = tid + p * 256;
            int r = f >> 3;
            int c4 = (f & 7) * 4;
            float4 v = make_float4(0.f, 0.f, 0.f, 0.f);
            if (row0 + r < M) v = *(const float4*)&A[(size_t)(row0 + r) * 128 + k0 + c4];
            As[r][c4 + 0] = f_tf32(v.x); As[r][c4 + 1] = f_tf32(v.y);
            As[r][c4 + 2] = f_tf32(v.z); As[r][c4 + 3] = f_tf32(v.w);
        }
        // B tile: 32 x 128 -> 1024 float4, 4 per thread
        #pragma unroll
        for (int p = 0; p < 4; p++) {
            int f = tid + p * 256;
            int kr = f >> 5;
            int c4 = (f & 31) * 4;
            float4 v = *(const float4*)&B[(size_t)(k0 + kr) * 128 + c4];
            Bs[kr][c4 + 0] = f_tf32(v.x); Bs[kr][c4 + 1] = f_tf32(v.y);
            Bs[kr][c4 + 2] = f_tf32(v.z); Bs[kr][c4 + 3] = f_tf32(v.w);
        }
        __syncthreads();

        #pragma unroll
        for (int ks = 0; ks < BK / 8; ks++) {
            int kb = ks * 8;
            uint32_t a[2][4];
            #pragma unroll
            for (int mi = 0; mi < 2; mi++) {
                int r = m0 + mi * 16 + grp;
                a[mi][0] = As[r    ][kb + tig    ];
                a[mi][1] = As[r + 8][kb + tig    ];
                a[mi][2] = As[r    ][kb + tig + 4];
                a[mi][3] = As[r + 8][kb + tig + 4];
            }
            uint32_t b[8][2];
            #pragma unroll
            for (int ni = 0; ni < 8; ni++) {
                int n = n0 + ni * 8 + grp;
                b[ni][0] = Bs[kb + tig    ][n];
                b[ni][1] = Bs[kb + tig + 4][n];
            }
            #pragma unroll
            for (int mi = 0; mi < 2; mi++)
                #pragma unroll
                for (int ni = 0; ni < 8; ni++) {
                    asm volatile(
                        "mma.sync.aligned.m16n8k8.row.col.f32.tf32.tf32.f32 "
                        "{%0,%1,%2,%3}, {%4,%5,%6,%7}, {%8,%9}, {%0,%1,%2,%3};"
                        : "+f"(acc[mi][ni][0]), "+f"(acc[mi][ni][1]),
                          "+f"(acc[mi][ni][2]), "+f"(acc[mi][ni][3])
                        : "r"(a[mi][0]), "r"(a[mi][1]), "r"(a[mi][2]), "r"(a[mi][3]),
                          "r"(b[ni][0]), "r"(b[ni][1]));
                }
        }
        __syncthreads();
    }

    // epilogue: c0,c1 -> (row, col..col+1), c2,c3 -> (row+8, col..col+1)
    #pragma unroll
    for (int mi = 0; mi < 2; mi++) {
        int rbase = row0 + m0 + mi * 16 + grp;
        #pragma unroll
        for (int ni = 0; ni < 8; ni++) {
            int col = n0 + ni * 8 + 2 * tig;
            if (rbase < M) {
                float2 v0 = make_float2(acc[mi][ni][0], acc[mi][ni][1]);
                *(float2*)&C[(size_t)rbase * 128 + col] = v0;
            }
            if (rbase + 8 < M) {
                float2 v1 = make_float2(acc[mi][ni][2], acc[mi][ni][3]);
                *(float2*)&C[(size_t)(rbase + 8) * 128 + col] = v1;
            }
        }
    }
}

// ---------------- SGEMM (R4 exact: single-buffer, BK=8) ---------------------
template <int N, int K, bool BNIN, bool BIAS>
__global__ __launch_bounds__(256) void sgemm_kernel(
    const float* __restrict__ A, const float* __restrict__ B, float* __restrict__ C,
    int M, const float* __restrict__ sc, const float* __restrict__ shf,
    const float* __restrict__ bias) {
    constexpr int BM = 128, BK = 8, TM = 8, TN = N / 16;
    __shared__ float As[BK][BM + 4];
    __shared__ float Bs[BK][N];
    __shared__ float s_sc[K], s_sh[K];

    int tid = threadIdx.x;
    if (BNIN) {
        for (int i = tid; i < K; i += 256) { s_sc[i] = sc[i]; s_sh[i] = shf[i]; }
    }
    __syncthreads();

    int tx = tid & 15, ty = tid >> 4;
    int row0 = blockIdx.x * BM;

    float acc[TM][TN];
    #pragma unroll
    for (int i = 0; i < TM; i++)
        #pragma unroll
        for (int j = 0; j < TN; j++) acc[i][j] = 0.f;

    int ar = tid >> 1;
    int ak = (tid & 1) * 4;
    int arow = row0 + ar;
    bool avalid = (arow < M);

    for (int k0 = 0; k0 < K; k0 += BK) {
        float4 av = make_float4(0.f, 0.f, 0.f, 0.f);
        if (avalid) av = *(const float4*)&A[(size_t)arow * K + k0 + ak];
        if (BNIN) {
            av.x = fmaxf(fmaf(av.x, s_sc[k0 + ak + 0], s_sh[k0 + ak + 0]), 0.f);
            av.y = fmaxf(fmaf(av.y, s_sc[k0 + ak + 1], s_sh[k0 + ak + 1]), 0.f);
            av.z = fmaxf(fmaf(av.z, s_sc[k0 + ak + 2], s_sh[k0 + ak + 2]), 0.f);
            av.w = fmaxf(fmaf(av.w, s_sc[k0 + ak + 3], s_sh[k0 + ak + 3]), 0.f);
        }
        As[ak + 0][ar] = av.x; As[ak + 1][ar] = av.y;
        As[ak + 2][ar] = av.z; As[ak + 3][ar] = av.w;

        #pragma unroll
        for (int i = tid; i < BK * N / 4; i += 256) {
            int kr = i / (N / 4);
            int c4 = (i % (N / 4)) * 4;
            *(float4*)&Bs[kr][c4] = *(const float4*)&B[(size_t)(k0 + kr) * N + c4];
        }
        __syncthreads();

        #pragma unroll
        for (int kk = 0; kk < BK; kk++) {
            float a[TM], b[TN];
            *(float4*)&a[0] = *(const float4*)&As[kk][ty * TM];
            *(float4*)&a[4] = *(const float4*)&As[kk][ty * TM + 4];
            #pragma unroll
            for (int j = 0; j < TN; j += 4)
                *(float4*)&b[j] = *(const float4*)&Bs[kk][tx * TN + j];
            #pragma unroll
            for (int i = 0; i < TM; i++)
                #pragma unroll
                for (int j = 0; j < TN; j++)
                    acc[i][j] = fmaf(a[i], b[j], acc[i][j]);
        }
        __syncthreads();
    }

    float bj[TN];
    if (BIAS) {
        #pragma unroll
        for (int j = 0; j < TN; j++) bj[j] = bias[tx * TN + j];
    }
    #pragma unroll
    for (int i = 0; i < TM; i++) {
        int grow = row0 + ty * TM + i;
        if (grow < M) {
            #pragma unroll
            for (int j = 0; j < TN; j += 4) {
                float4 v;
                v.x = acc[i][j]; v.y = acc[i][j + 1];
                v.z = acc[i][j + 2]; v.w = acc[i][j + 3];
                if (BIAS) { v.x += bj[j]; v.y += bj[j + 1]; v.z += bj[j + 2]; v.w += bj[j + 3]; }
                *(float4*)&C[(size_t)grow * N + tx * TN + j] = v;
            }
        }
    }
}

// ---------------- launch ----------------------------------------------------
extern "C" void kernel_launch(void* const* d_in, const int* in_sizes, int n_in,
                              void* d_out, int out_size) {
    const float* x     = (const float*)d_in[0];
    const int*   ei    = (const int*)d_in[1];
    const float* W_gcn = (const float*)d_in[2];
    // d_in[3] = b_gcn : exactly absorbed by BN1 (mean-subtraction) -> unused
    const float* bn_g  = (const float*)d_in[4];
    const float* bn_b  = (const float*)d_in[5];
    const float* W1    = (const float*)d_in[6];
    // d_in[7] = b1    : exactly absorbed by BN2 -> unused
    const float* mg    = (const float*)d_in[8];
    const float* mb    = (const float*)d_in[9];
    const float* W2    = (const float*)d_in[10];
    const float* b2    = (const float*)d_in[11];
    float* out = (float*)d_out;

    int M = in_sizes[0] / FIN;
    int E = in_sizes[1] / 2;
    const int* src = ei;
    const int* dst = ei + E;
    int NB = (M + SCAN_BS - 1) / SCAN_BS;

    void *p_h, *p_agg, *p_t, *p_sum1, *p_sq1, *p_a1, *p_c1, *p_sum2, *p_sq2, *p_a2, *p_c2;
    cudaGetSymbolAddress(&p_h, g_h);
    cudaGetSymbolAddress(&p_agg, g_agg);
    cudaGetSymbolAddress(&p_t, g_t);
    cudaGetSymbolAddress(&p_sum1, g_sum1);
    cudaGetSymbolAddress(&p_sq1, g_sq1);
    cudaGetSymbolAddress(&p_a1, g_a1);
    cudaGetSymbolAddress(&p_c1, g_c1);
    cudaGetSymbolAddress(&p_sum2, g_sum2);
    cudaGetSymbolAddress(&p_sq2, g_sq2);
    cudaGetSymbolAddress(&p_a2, g_a2);
    cudaGetSymbolAddress(&p_c2, g_c2);

    // index machinery
    zero_kernel<<<256, 256>>>(M);
    deg_kernel<<<(E + 255) / 256, 256>>>(dst, E, M);
    scan1_kernel<<<NB, SCAN_BS>>>(M);
    scan2_kernel<<<1, MAX_BLOCKS>>>(NB);
    scan3_kernel<<<NB, SCAN_BS>>>(M, E);
    fill_kernel<<<(E + 255) / 256, 256>>>(src, dst, E, M);

    // GEMM1 (tf32 tensor cores): h = x @ W_gcn
    tgemm1_kernel<<<(M + 127) / 128, 256>>>(x, W_gcn, (float*)p_h, M);

    // CSR gather
    gather_kernel<<<(M * 32 + 255) / 256, 256>>>(M);

    // BN1 stats
    stats_kernel<FIN><<<1024, 256>>>((const float*)p_agg, M, (float*)p_sum1, (float*)p_sq1);
    finalize_kernel<FIN><<<1, 128>>>((const float*)p_sum1, (const float*)p_sq1,
                                     bn_g, bn_b, M, (float*)p_a1, (float*)p_c1);

    // GEMM2: t = relu(BN1(agg)) @ W1   (b1 absorbed by BN2)
    sgemm_kernel<FOUT, FIN, true, false><<<(M + 127) / 128, 256>>>(
        (const float*)p_agg, W1, (float*)p_t, M,
        (const float*)p_a1, (const float*)p_c1, nullptr);

    // BN2 stats
    stats_kernel<FOUT><<<1024, 256>>>((const float*)p_t, M, (float*)p_sum2, (float*)p_sq2);
    finalize_kernel<FOUT><<<1, 64>>>((const float*)p_sum2, (const float*)p_sq2,
                                     mg, mb, M, (float*)p_a2, (float*)p_c2);

    // GEMM3: out = relu(BN2(t)) @ W2 + b2
    sgemm_kernel<FOUT, FOUT, true, true><<<(M + 127) / 128, 256>>>(
        (const float*)p_t, W2, out, M,
        (const float*)p_a2, (const float*)p_c2, b2);
}

// round 9
// speedup vs baseline: 1.6337x; 1.1089x over previous
#include <cuda_runtime.h>
#include <cstdint>

#define NNODES 100000
#define NEDGES 640000
#define FIN 128
#define FOUT 64
#define BN_EPS 1e-5f
#define SCAN_BS 256
#define MAX_BLOCKS 512   // ceil(NNODES/SCAN_BS) = 391 < 512

// ---------------- scratch (static device globals; no runtime allocation) ----
__device__ float g_h[(size_t)NNODES * FIN];     // x @ W_gcn
__device__ float g_agg[(size_t)NNODES * FIN];   // aggregated messages
__device__ float g_t[(size_t)NNODES * FOUT];    // hidden after GEMM2
__device__ int   g_degi[NNODES];
__device__ float g_dinv[NNODES];
__device__ int   g_off[NNODES + 1];
__device__ int   g_cursor[NNODES];
__device__ int   g_bsum[MAX_BLOCKS];
__device__ int   g_boff[MAX_BLOCKS];
__device__ int   g_elist[NEDGES];
__device__ float g_sum1[FIN], g_sq1[FIN], g_a1[FIN], g_c1[FIN];
__device__ float g_sum2[FOUT], g_sq2[FOUT], g_a2[FOUT], g_c2[FOUT];

// ---------------- zero ------------------------------------------------------
__global__ void zero_kernel(int M) {
    int i = blockIdx.x * blockDim.x + threadIdx.x;
    for (int j = i; j < M; j += gridDim.x * blockDim.x) g_degi[j] = 0;
    if (i < FIN)  { g_sum1[i] = 0.f; g_sq1[i] = 0.f; }
    if (i < FOUT) { g_sum2[i] = 0.f; g_sq2[i] = 0.f; }
}

// ---------------- in-degree count -------------------------------------------
__global__ void deg_kernel(const int* __restrict__ dst, int E, int M) {
    int e = blockIdx.x * blockDim.x + threadIdx.x;
    if (e < E) {
        int d = dst[e];
        if ((unsigned)d < (unsigned)M) atomicAdd(&g_degi[d], 1);
    }
}

// ---------------- prefix scan (3 kernels) -----------------------------------
__global__ void scan1_kernel(int M) {
    __shared__ int sh[SCAN_BS];
    int i = blockIdx.x * SCAN_BS + threadIdx.x;
    int v = (i < M) ? g_degi[i] : 0;
    sh[threadIdx.x] = v;
    __syncthreads();
    #pragma unroll
    for (int ofs = 1; ofs < SCAN_BS; ofs <<= 1) {
        int t = 0;
        if (threadIdx.x >= ofs) t = sh[threadIdx.x - ofs];
        __syncthreads();
        sh[threadIdx.x] += t;
        __syncthreads();
    }
    if (i < M) g_off[i] = sh[threadIdx.x] - v;
    if (threadIdx.x == SCAN_BS - 1) g_bsum[blockIdx.x] = sh[SCAN_BS - 1];
}

__global__ void scan2_kernel(int NB) {
    __shared__ int sh[MAX_BLOCKS];
    int t = threadIdx.x;
    int v = (t < NB) ? g_bsum[t] : 0;
    sh[t] = v;
    __syncthreads();
    #pragma unroll
    for (int ofs = 1; ofs < MAX_BLOCKS; ofs <<= 1) {
        int u = 0;
        if (t >= ofs) u = sh[t - ofs];
        __syncthreads();
        sh[t] += u;
        __syncthreads();
    }
    if (t < NB) g_boff[t] = sh[t] - v;
}

__global__ void scan3_kernel(int M, int E) {
    int i = blockIdx.x * blockDim.x + threadIdx.x;
    if (i < M) {
        int o = g_off[i] + g_boff[i / SCAN_BS];
        g_off[i] = o;
        g_cursor[i] = o;
        g_dinv[i] = rsqrtf((float)g_degi[i] + 1.0f);  // +1 = self loop
    }
    if (i == 0) g_off[M] = E;
}

// ---------------- edge-list fill --------------------------------------------
__global__ void fill_kernel(const int* __restrict__ src, const int* __restrict__ dst,
                            int E, int M) {
    int e = blockIdx.x * blockDim.x + threadIdx.x;
    if (e < E) {
        int s = src[e];
        int d = dst[e];
        if ((unsigned)s < (unsigned)M && (unsigned)d < (unsigned)M) {
            int p = atomicAdd(&g_cursor[d], 1);
            g_elist[p] = s;
        }
    }
}

// ---------------- gather (R4 exact) -----------------------------------------
__global__ void gather_kernel(int M) {
    int warp = (blockIdx.x * blockDim.x + threadIdx.x) >> 5;
    int lane = threadIdx.x & 31;
    if (warp >= M) return;
    int d = warp;
    int e0 = g_off[d];
    int e1 = g_cursor[d];
    float4 acc = make_float4(0.f, 0.f, 0.f, 0.f);
    for (int e = e0; e < e1; e++) {
        int s = g_elist[e];
        float ws = g_dinv[s];
        float4 v = *(const float4*)&g_h[(size_t)s * FIN + lane * 4];
        acc.x = fmaf(v.x, ws, acc.x);
        acc.y = fmaf(v.y, ws, acc.y);
        acc.z = fmaf(v.z, ws, acc.z);
        acc.w = fmaf(v.w, ws, acc.w);
    }
    float wd = g_dinv[d];
    float4 vs = *(const float4*)&g_h[(size_t)d * FIN + lane * 4];
    float4 o;
    o.x = wd * acc.x + wd * wd * vs.x;
    o.y = wd * acc.y + wd * wd * vs.y;
    o.z = wd * acc.z + wd * wd * vs.z;
    o.w = wd * acc.w + wd * wd * vs.w;
    *(float4*)&g_agg[(size_t)d * FIN + lane * 4] = o;
}

// ---------------- per-column sum / sumsq ------------------------------------
template <int F>
__global__ void stats_kernel(const float* __restrict__ X, int M,
                             float* __restrict__ sum, float* __restrict__ sq) {
    constexpr int RP = 256 / F;
    int col  = threadIdx.x % F;
    int rsub = threadIdx.x / F;
    float s = 0.f, q = 0.f;
    for (int r = blockIdx.x * RP + rsub; r < M; r += gridDim.x * RP) {
        float v = X[(size_t)r * F + col];
        s += v; q += v * v;
    }
    __shared__ float sh[256];
    sh[threadIdx.x] = s; __syncthreads();
    if (rsub == 0) {
        #pragma unroll
        for (int k = 1; k < RP; k++) s += sh[k * F + col];
    }
    __syncthreads();
    sh[threadIdx.x] = q; __syncthreads();
    if (rsub == 0) {
        #pragma unroll
        for (int k = 1; k < RP; k++) q += sh[k * F + col];
        atomicAdd(&sum[col], s);
        atomicAdd(&sq[col],  q);
    }
}

template <int F>
__global__ void finalize_kernel(const float* __restrict__ sum, const float* __restrict__ sq,
                                const float* __restrict__ gamma, const float* __restrict__ beta,
                                int M, float* __restrict__ a, float* __restrict__ c) {
    int i = threadIdx.x;
    if (i < F) {
        float mean = sum[i] / (float)M;
        float var  = sq[i] / (float)M - mean * mean;
        float s = gamma[i] * rsqrtf(var + BN_EPS);
        a[i] = s;
        c[i] = beta[i] - mean * s;
    }
}

// ---------------- tf32 helpers ----------------------------------------------
__device__ __forceinline__ uint32_t f_tf32(float x) {
    uint32_t y;
    asm("cvt.rna.tf32.f32 %0, %1;" : "=r"(y) : "f"(x));
    return y;
}

// ---------------- tf32 tensor GEMM1: h = x @ W  (M x 128 x 128) -------------
__global__ __launch_bounds__(256) void tgemm1_kernel(
    const float* __restrict__ A, const float* __restrict__ B, float* __restrict__ C, int M) {
    constexpr int BM = 128, BN = 128, BK = 32;
    __shared__ uint32_t As[BM][BK + 4];
    __shared__ uint32_t Bs[BK][BN + 8];

    int tid = threadIdx.x;
    int lane = tid & 31, wid = tid >> 5;
    int wr = wid & 3, wc = wid >> 2;        // warp tile: 32 rows x 64 cols
    int m0 = wr * 32, n0 = wc * 64;
    int row0 = blockIdx.x * BM;
    int grp = lane >> 2, tig = lane & 3;

    float acc[2][8][4];
    #pragma unroll
    for (int i = 0; i < 2; i++)
        #pragma unroll
        for (int j = 0; j < 8; j++)
            #pragma unroll
            for (int r = 0; r < 4; r++) acc[i][j][r] = 0.f;

    for (int k0 = 0; k0 < 128; k0 += BK) {
        #pragma unroll
        for (int p = 0; p < 4; p++) {
            int f = tid + p * 256;
            int r = f >> 3;
            int c4 = (f & 7) * 4;
            float4 v = make_float4(0.f, 0.f, 0.f, 0.f);
            if (row0 + r < M) v = *(const float4*)&A[(size_t)(row0 + r) * 128 + k0 + c4];
            As[r][c4 + 0] = f_tf32(v.x); As[r][c4 + 1] = f_tf32(v.y);
            As[r][c4 + 2] = f_tf32(v.z); As[r][c4 + 3] = f_tf32(v.w);
        }
        #pragma unroll
        for (int p = 0; p < 4; p++) {
            int f = tid + p * 256;
            int kr = f >> 5;
            int c4 = (f & 31) * 4;
            float4 v = *(const float4*)&B[(size_t)(k0 + kr) * 128 + c4];
            Bs[kr][c4 + 0] = f_tf32(v.x); Bs[kr][c4 + 1] = f_tf32(v.y);
            Bs[kr][c4 + 2] = f_tf32(v.z); Bs[kr][c4 + 3] = f_tf32(v.w);
        }
        __syncthreads();

        #pragma unroll
        for (int ks = 0; ks < BK / 8; ks++) {
            int kb = ks * 8;
            uint32_t a[2][4];
            #pragma unroll
            for (int mi = 0; mi < 2; mi++) {
                int r = m0 + mi * 16 + grp;
                a[mi][0] = As[r    ][kb + tig    ];
                a[mi][1] = As[r + 8][kb + tig    ];
                a[mi][2] = As[r    ][kb + tig + 4];
                a[mi][3] = As[r + 8][kb + tig + 4];
            }
            uint32_t b[8][2];
            #pragma unroll
            for (int ni = 0; ni < 8; ni++) {
                int n = n0 + ni * 8 + grp;
                b[ni][0] = Bs[kb + tig    ][n];
                b[ni][1] = Bs[kb + tig + 4][n];
            }
            #pragma unroll
            for (int mi = 0; mi < 2; mi++)
                #pragma unroll
                for (int ni = 0; ni < 8; ni++) {
                    asm volatile(
                        "mma.sync.aligned.m16n8k8.row.col.f32.tf32.tf32.f32 "
                        "{%0,%1,%2,%3}, {%4,%5,%6,%7}, {%8,%9}, {%0,%1,%2,%3};"
                        : "+f"(acc[mi][ni][0]), "+f"(acc[mi][ni][1]),
                          "+f"(acc[mi][ni][2]), "+f"(acc[mi][ni][3])
                        : "r"(a[mi][0]), "r"(a[mi][1]), "r"(a[mi][2]), "r"(a[mi][3]),
                          "r"(b[ni][0]), "r"(b[ni][1]));
                }
        }
        __syncthreads();
    }

    #pragma unroll
    for (int mi = 0; mi < 2; mi++) {
        int rbase = row0 + m0 + mi * 16 + grp;
        #pragma unroll
        for (int ni = 0; ni < 8; ni++) {
            int col = n0 + ni * 8 + 2 * tig;
            if (rbase < M) {
                float2 v0 = make_float2(acc[mi][ni][0], acc[mi][ni][1]);
                *(float2*)&C[(size_t)rbase * 128 + col] = v0;
            }
            if (rbase + 8 < M) {
                float2 v1 = make_float2(acc[mi][ni][2], acc[mi][ni][3]);
                *(float2*)&C[(size_t)(rbase + 8) * 128 + col] = v1;
            }
        }
    }
}

// ---------------- tf32 tensor GEMM2: t = relu(a*agg+c) @ W1 (M x 128 x 64) --
__global__ __launch_bounds__(256) void tgemm2_kernel(
    const float* __restrict__ A, const float* __restrict__ B, float* __restrict__ C,
    int M, const float* __restrict__ sc, const float* __restrict__ shf) {
    constexpr int BM = 128, BN = 64, BK = 32, K = 128;
    __shared__ uint32_t As[BM][BK + 4];
    __shared__ uint32_t Bs[BK][BN + 8];
    __shared__ float s_sc[K], s_sh[K];

    int tid = threadIdx.x;
    if (tid < K) { s_sc[tid] = sc[tid]; s_sh[tid] = shf[tid]; }

    int lane = tid & 31, wid = tid >> 5;
    int wr = wid & 3, wc = wid >> 2;        // warp tile: 32 rows x 32 cols
    int m0 = wr * 32, n0 = wc * 32;
    int row0 = blockIdx.x * BM;
    int grp = lane >> 2, tig = lane & 3;
    __syncthreads();

    float acc[2][4][4];
    #pragma unroll
    for (int i = 0; i < 2; i++)
        #pragma unroll
        for (int j = 0; j < 4; j++)
            #pragma unroll
            for (int r = 0; r < 4; r++) acc[i][j][r] = 0.f;

    for (int k0 = 0; k0 < K; k0 += BK) {
        // A tile 128x32: BN+ReLU fused, then tf32
        #pragma unroll
        for (int p = 0; p < 4; p++) {
            int f = tid + p * 256;
            int r = f >> 3;
            int c4 = (f & 7) * 4;
            float4 v = make_float4(0.f, 0.f, 0.f, 0.f);
            if (row0 + r < M) v = *(const float4*)&A[(size_t)(row0 + r) * K + k0 + c4];
            int kb = k0 + c4;
            v.x = fmaxf(fmaf(v.x, s_sc[kb + 0], s_sh[kb + 0]), 0.f);
            v.y = fmaxf(fmaf(v.y, s_sc[kb + 1], s_sh[kb + 1]), 0.f);
            v.z = fmaxf(fmaf(v.z, s_sc[kb + 2], s_sh[kb + 2]), 0.f);
            v.w = fmaxf(fmaf(v.w, s_sc[kb + 3], s_sh[kb + 3]), 0.f);
            As[r][c4 + 0] = f_tf32(v.x); As[r][c4 + 1] = f_tf32(v.y);
            As[r][c4 + 2] = f_tf32(v.z); As[r][c4 + 3] = f_tf32(v.w);
        }
        // B tile 32x64 -> 512 float4, 2 per thread
        #pragma unroll
        for (int p = 0; p < 2; p++) {
            int f = tid + p * 256;
            int kr = f >> 4;
            int c4 = (f & 15) * 4;
            float4 v = *(const float4*)&B[(size_t)(k0 + kr) * BN + c4];
            Bs[kr][c4 + 0] = f_tf32(v.x); Bs[kr][c4 + 1] = f_tf32(v.y);
            Bs[kr][c4 + 2] = f_tf32(v.z); Bs[kr][c4 + 3] = f_tf32(v.w);
        }
        __syncthreads();

        #pragma unroll
        for (int ks = 0; ks < BK / 8; ks++) {
            int kb = ks * 8;
            uint32_t a[2][4];
            #pragma unroll
            for (int mi = 0; mi < 2; mi++) {
                int r = m0 + mi * 16 + grp;
                a[mi][0] = As[r    ][kb + tig    ];
                a[mi][1] = As[r + 8][kb + tig    ];
                a[mi][2] = As[r    ][kb + tig + 4];
                a[mi][3] = As[r + 8][kb + tig + 4];
            }
            uint32_t b[4][2];
            #pragma unroll
            for (int ni = 0; ni < 4; ni++) {
                int n = n0 + ni * 8 + grp;
                b[ni][0] = Bs[kb + tig    ][n];
                b[ni][1] = Bs[kb + tig + 4][n];
            }
            #pragma unroll
            for (int mi = 0; mi < 2; mi++)
                #pragma unroll
                for (int ni = 0; ni < 4; ni++) {
                    asm volatile(
                        "mma.sync.aligned.m16n8k8.row.col.f32.tf32.tf32.f32 "
                        "{%0,%1,%2,%3}, {%4,%5,%6,%7}, {%8,%9}, {%0,%1,%2,%3};"
                        : "+f"(acc[mi][ni][0]), "+f"(acc[mi][ni][1]),
                          "+f"(acc[mi][ni][2]), "+f"(acc[mi][ni][3])
                        : "r"(a[mi][0]), "r"(a[mi][1]), "r"(a[mi][2]), "r"(a[mi][3]),
                          "r"(b[ni][0]), "r"(b[ni][1]));
                }
        }
        __syncthreads();
    }

    #pragma unroll
    for (int mi = 0; mi < 2; mi++) {
        int rbase = row0 + m0 + mi * 16 + grp;
        #pragma unroll
        for (int ni = 0; ni < 4; ni++) {
            int col = n0 + ni * 8 + 2 * tig;
            if (rbase < M) {
                float2 v0 = make_float2(acc[mi][ni][0], acc[mi][ni][1]);
                *(float2*)&C[(size_t)rbase * BN + col] = v0;
            }
            if (rbase + 8 < M) {
                float2 v1 = make_float2(acc[mi][ni][2], acc[mi][ni][3]);
                *(float2*)&C[(size_t)(rbase + 8) * BN + col] = v1;
            }
        }
    }
}

// ---------------- SGEMM (R4 exact: single-buffer, BK=8) ---------------------
template <int N, int K, bool BNIN, bool BIAS>
__global__ __launch_bounds__(256) void sgemm_kernel(
    const float* __restrict__ A, const float* __restrict__ B, float* __restrict__ C,
    int M, const float* __restrict__ sc, const float* __restrict__ shf,
    const float* __restrict__ bias) {
    constexpr int BM = 128, BK = 8, TM = 8, TN = N / 16;
    __shared__ float As[BK][BM + 4];
    __shared__ float Bs[BK][N];
    __shared__ float s_sc[K], s_sh[K];

    int tid = threadIdx.x;
    if (BNIN) {
        for (int i = tid; i < K; i += 256) { s_sc[i] = sc[i]; s_sh[i] = shf[i]; }
    }
    __syncthreads();

    int tx = tid & 15, ty = tid >> 4;
    int row0 = blockIdx.x * BM;

    float acc[TM][TN];
    #pragma unroll
    for (int i = 0; i < TM; i++)
        #pragma unroll
        for (int j = 0; j < TN; j++) acc[i][j] = 0.f;

    int ar = tid >> 1;
    int ak = (tid & 1) * 4;
    int arow = row0 + ar;
    bool avalid = (arow < M);

    for (int k0 = 0; k0 < K; k0 += BK) {
        float4 av = make_float4(0.f, 0.f, 0.f, 0.f);
        if (avalid) av = *(const float4*)&A[(size_t)arow * K + k0 + ak];
        if (BNIN) {
            av.x = fmaxf(fmaf(av.x, s_sc[k0 + ak + 0], s_sh[k0 + ak + 0]), 0.f);
            av.y = fmaxf(fmaf(av.y, s_sc[k0 + ak + 1], s_sh[k0 + ak + 1]), 0.f);
            av.z = fmaxf(fmaf(av.z, s_sc[k0 + ak + 2], s_sh[k0 + ak + 2]), 0.f);
            av.w = fmaxf(fmaf(av.w, s_sc[k0 + ak + 3], s_sh[k0 + ak + 3]), 0.f);
        }
        As[ak + 0][ar] = av.x; As[ak + 1][ar] = av.y;
        As[ak + 2][ar] = av.z; As[ak + 3][ar] = av.w;

        #pragma unroll
        for (int i = tid; i < BK * N / 4; i += 256) {
            int kr = i / (N / 4);
            int c4 = (i % (N / 4)) * 4;
            *(float4*)&Bs[kr][c4] = *(const float4*)&B[(size_t)(k0 + kr) * N + c4];
        }
        __syncthreads();

        #pragma unroll
        for (int kk = 0; kk < BK; kk++) {
            float a[TM], b[TN];
            *(float4*)&a[0] = *(const float4*)&As[kk][ty * TM];
            *(float4*)&a[4] = *(const float4*)&As[kk][ty * TM + 4];
            #pragma unroll
            for (int j = 0; j < TN; j += 4)
                *(float4*)&b[j] = *(const float4*)&Bs[kk][tx * TN + j];
            #pragma unroll
            for (int i = 0; i < TM; i++)
                #pragma unroll
                for (int j = 0; j < TN; j++)
                    acc[i][j] = fmaf(a[i], b[j], acc[i][j]);
        }
        __syncthreads();
    }

    float bj[TN];
    if (BIAS) {
        #pragma unroll
        for (int j = 0; j < TN; j++) bj[j] = bias[tx * TN + j];
    }
    #pragma unroll
    for (int i = 0; i < TM; i++) {
        int grow = row0 + ty * TM + i;
        if (grow < M) {
            #pragma unroll
            for (int j = 0; j < TN; j += 4) {
                float4 v;
                v.x = acc[i][j]; v.y = acc[i][j + 1];
                v.z = acc[i][j + 2]; v.w = acc[i][j + 3];
                if (BIAS) { v.x += bj[j]; v.y += bj[j + 1]; v.z += bj[j + 2]; v.w += bj[j + 3]; }
                *(float4*)&C[(size_t)grow * N + tx * TN + j] = v;
            }
        }
    }
}

// ---------------- launch ----------------------------------------------------
extern "C" void kernel_launch(void* const* d_in, const int* in_sizes, int n_in,
                              void* d_out, int out_size) {
    const float* x     = (const float*)d_in[0];
    const int*   ei    = (const int*)d_in[1];
    const float* W_gcn = (const float*)d_in[2];
    // d_in[3] = b_gcn : exactly absorbed by BN1 (mean-subtraction) -> unused
    const float* bn_g  = (const float*)d_in[4];
    const float* bn_b  = (const float*)d_in[5];
    const float* W1    = (const float*)d_in[6];
    // d_in[7] = b1    : exactly absorbed by BN2 -> unused
    const float* mg    = (const float*)d_in[8];
    const float* mb    = (const float*)d_in[9];
    const float* W2    = (const float*)d_in[10];
    const float* b2    = (const float*)d_in[11];
    float* out = (float*)d_out;

    int M = in_sizes[0] / FIN;
    int E = in_sizes[1] / 2;
    const int* src = ei;
    const int* dst = ei + E;
    int NB = (M + SCAN_BS - 1) / SCAN_BS;

    void *p_h, *p_agg, *p_t, *p_sum1, *p_sq1, *p_a1, *p_c1, *p_sum2, *p_sq2, *p_a2, *p_c2;
    cudaGetSymbolAddress(&p_h, g_h);
    cudaGetSymbolAddress(&p_agg, g_agg);
    cudaGetSymbolAddress(&p_t, g_t);
    cudaGetSymbolAddress(&p_sum1, g_sum1);
    cudaGetSymbolAddress(&p_sq1, g_sq1);
    cudaGetSymbolAddress(&p_a1, g_a1);
    cudaGetSymbolAddress(&p_c1, g_c1);
    cudaGetSymbolAddress(&p_sum2, g_sum2);
    cudaGetSymbolAddress(&p_sq2, g_sq2);
    cudaGetSymbolAddress(&p_a2, g_a2);
    cudaGetSymbolAddress(&p_c2, g_c2);

    // index machinery
    zero_kernel<<<256, 256>>>(M);
    deg_kernel<<<(E + 255) / 256, 256>>>(dst, E, M);
    scan1_kernel<<<NB, SCAN_BS>>>(M);
    scan2_kernel<<<1, MAX_BLOCKS>>>(NB);
    scan3_kernel<<<NB, SCAN_BS>>>(M, E);
    fill_kernel<<<(E + 255) / 256, 256>>>(src, dst, E, M);

    // GEMM1 (tf32 tensor cores): h = x @ W_gcn
    tgemm1_kernel<<<(M + 127) / 128, 256>>>(x, W_gcn, (float*)p_h, M);

    // CSR gather
    gather_kernel<<<(M * 32 + 255) / 256, 256>>>(M);

    // BN1 stats
    stats_kernel<FIN><<<1024, 256>>>((const float*)p_agg, M, (float*)p_sum1, (float*)p_sq1);
    finalize_kernel<FIN><<<1, 128>>>((const float*)p_sum1, (const float*)p_sq1,
                                     bn_g, bn_b, M, (float*)p_a1, (float*)p_c1);

    // GEMM2 (tf32 tensor cores): t = relu(BN1(agg)) @ W1  (b1 absorbed by BN2)
    tgemm2_kernel<<<(M + 127) / 128, 256>>>(
        (const float*)p_agg, W1, (float*)p_t, M,
        (const float*)p_a1, (const float*)p_c1);

    // BN2 stats
    stats_kernel<FOUT><<<1024, 256>>>((const float*)p_t, M, (float*)p_sum2, (float*)p_sq2);
    finalize_kernel<FOUT><<<1, 64>>>((const float*)p_sum2, (const float*)p_sq2,
                                     mg, mb, M, (float*)p_a2, (float*)p_c2);

    // GEMM3 (exact fp32): out = relu(BN2(t)) @ W2 + b2
    sgemm_kernel<FOUT, FOUT, true, true><<<(M + 127) / 128, 256>>>(
        (const float*)p_t, W2, out, M,
        (const float*)p_a2, (const float*)p_c2, b2);
}